// round 6
// baseline (speedup 1.0000x reference)
#include <cuda_runtime.h>
#include <math.h>

#define DD 256
#define BATCH 4
#define NN 512

typedef unsigned long long u64;

// Scratch: xp = x @ Wx  (B*N, D);  ypb = y @ Wy + b1  (B*N, D)
__device__ float g_xp[BATCH * NN * DD];
__device__ float g_ypb[BATCH * NN * DD];

// ---- f32x2 packed-math primitives (fma pipe, 2 fp32 per slot) -------------
#define F2FMA(D_, A_, B_, C_) \
    asm("fma.rn.f32x2 %0, %1, %2, %3;" : "=l"(D_) : "l"(A_), "l"(B_), "l"(C_))
#define F2ADD(D_, A_, B_) \
    asm("add.rn.f32x2 %0, %1, %2;" : "=l"(D_) : "l"(A_), "l"(B_))
#define F2MUL(D_, A_, B_) \
    asm("mul.rn.f32x2 %0, %1, %2;" : "=l"(D_) : "l"(A_), "l"(B_))
#define PK(D_, LO_, HI_) \
    asm("mov.b64 %0, {%1, %2};" : "=l"(D_) : "f"(LO_), "f"(HI_))
#define UNPK(LO_, HI_, S_) \
    asm("mov.b64 {%0, %1}, %2;" : "=f"(LO_), "=f"(HI_) : "l"(S_))

__device__ __forceinline__ float tanh_fast(float v) {
    float r;
    asm("tanh.approx.f32 %0, %1;" : "=f"(r) : "f"(v));
    return r;
}

#define GC0 0.79788456080286536f          // sqrt(2/pi)
#define GC1 0.03567740813636141f          // sqrt(2/pi)*0.044715

// ---------------------------------------------------------------------------
// Merged GEMM: z=0: g_xp = x @ W1[0:256];  z=1: g_ypb = y @ W1[256:512] + b1
// M=2048, tiles 64x64, BK=16, 256 threads, 4x4 per thread, f32x2 inner.
// ---------------------------------------------------------------------------
__global__ __launch_bounds__(256) void gemm_kernel(
    const float* __restrict__ x,
    const float* __restrict__ y,
    const float* __restrict__ W1,
    const float* __restrict__ b1)
{
    __shared__ float Asd[16][138];   // [k][2m], [k][2m+1] = A[m][k] (dup)
    __shared__ float Bs[16][68];

    const int sel = blockIdx.z;
    const float* X = sel ? y : x;
    const float* W = sel ? (W1 + 256 * 256) : W1;
    float* out = sel ? g_ypb : g_xp;

    const int tx = threadIdx.x;     // 0..15
    const int ty = threadIdx.y;     // 0..15
    const int t  = ty * 16 + tx;
    const int m0 = blockIdx.y * 64;
    const int n0 = blockIdx.x * 64;

    u64 acc[4][2];
    #pragma unroll
    for (int i = 0; i < 4; ++i) { acc[i][0] = 0ull; acc[i][1] = 0ull; }

    for (int k0 = 0; k0 < 256; k0 += 16) {
        {
            int m  = t >> 2;              // 0..63
            int kq = (t & 3) * 4;         // 0,4,8,12
            float4 v = *(const float4*)&X[(m0 + m) * 256 + k0 + kq];
            u64 p;
            PK(p, v.x, v.x); *(u64*)&Asd[kq + 0][2 * m] = p;
            PK(p, v.y, v.y); *(u64*)&Asd[kq + 1][2 * m] = p;
            PK(p, v.z, v.z); *(u64*)&Asd[kq + 2][2 * m] = p;
            PK(p, v.w, v.w); *(u64*)&Asd[kq + 3][2 * m] = p;
        }
        {
            int k  = t >> 4;              // 0..15
            int nq = (t & 15) * 4;        // 0..60
            float4 v = *(const float4*)&W[(k0 + k) * 256 + n0 + nq];
            *(float4*)&Bs[k][nq] = v;
        }
        __syncthreads();

        #pragma unroll
        for (int kk = 0; kk < 16; ++kk) {
            const float* ar = &Asd[kk][0];
            const float* br = &Bs[kk][0];
            u64 B0 = *(const u64*)&br[tx * 4];
            u64 B1 = *(const u64*)&br[tx * 4 + 2];
            #pragma unroll
            for (int i = 0; i < 4; ++i) {
                u64 Ai = *(const u64*)&ar[2 * (ty * 4 + i)];
                F2FMA(acc[i][0], Ai, B0, acc[i][0]);
                F2FMA(acc[i][1], Ai, B1, acc[i][1]);
            }
        }
        __syncthreads();
    }

    #pragma unroll
    for (int i = 0; i < 4; ++i) {
        int m = m0 + ty * 4 + i;
        int n = n0 + tx * 4;
        float c0, c1, c2, c3;
        UNPK(c0, c1, acc[i][0]);
        UNPK(c2, c3, acc[i][1]);
        if (sel) {
            c0 += b1[n + 0]; c1 += b1[n + 1];
            c2 += b1[n + 2]; c3 += b1[n + 3];
        }
        float4 o = {c0, c1, c2, c3};
        *(float4*)&out[m * 256 + n] = o;
    }
}

// ---------------------------------------------------------------------------
// Cross kernel: block = (b, 32n x 32m) tile; thread = 2x2 micro-tile packed
// as two f32x2 groups. d chunked 2x128 -> 6 blocks/SM.
// acc0 path: f32 tanh (2 MUFU); acc1 path: f16x2 tanh (1 MUFU).
// ---------------------------------------------------------------------------
#define SX 34       // row stride (floats): even for LDS.64 align, conflict-free
#define DCH 128     // d-chunk

__global__ __launch_bounds__(256, 6) void cross_kernel(
    const float* __restrict__ W2,
    const float* __restrict__ b2,
    float* __restrict__ out)
{
    extern __shared__ float sm[];
    float* xs  = sm;                     // [DCH][SX], d-major within chunk
    float* ys  = sm + DCH * SX;          // [DCH][SX]
    float* ws2 = sm + 2 * DCH * SX;      // [512] duplicated (0.5*W2 pairs)

    const int tx = threadIdx.x;        // 0..15 -> m
    const int ty = threadIdx.y;        // 0..15 -> n
    const int t  = ty * 16 + tx;
    const int bz = blockIdx.z;
    const int n0 = blockIdx.y * 32;
    const int m0 = blockIdx.x * 32;

    const float* xp = g_xp  + (bz * NN + n0) * DD;
    const float* yp = g_ypb + (bz * NN + m0) * DD;

    // ws2 once (all 256 d)
    {
        float wv = 0.5f * W2[t];
        u64 wp; PK(wp, wv, wv);
        *(u64*)&ws2[2 * t] = wp;
    }

    u64 C0P, C1P;
    PK(C0P, GC0, GC0);
    PK(C1P, GC1, GC1);

    u64 acc0 = 0ull, acc1 = 0ull;   // (a00,a01), (a10,a11)

    const int r  = t >> 3;    // 0..31
    const int cq = t & 7;     // 0..7
    const float* xsp = xs + 2 * ty;
    const float* ysp = ys + 2 * tx;

    #pragma unroll
    for (int c = 0; c < 2; ++c) {
        __syncthreads();   // (c=1: protect prior chunk's reads before refill)
        // Conflict-free transpose fill of this 128-d chunk
        #pragma unroll
        for (int it = 0; it < 4; ++it) {
            int dl = 32 * it + 4 * cq;           // 0..124 within chunk
            int dg = c * DCH + dl;               // global d
            float4 v = *(const float4*)&xp[r * 256 + dg];
            xs[(dl + 0) * SX + r] = v.x;
            xs[(dl + 1) * SX + r] = v.y;
            xs[(dl + 2) * SX + r] = v.z;
            xs[(dl + 3) * SX + r] = v.w;
            float4 u = *(const float4*)&yp[r * 256 + dg];
            ys[(dl + 0) * SX + r] = u.x;
            ys[(dl + 1) * SX + r] = u.y;
            ys[(dl + 2) * SX + r] = u.z;
            ys[(dl + 3) * SX + r] = u.w;
        }
        __syncthreads();

        const float* wc = ws2 + c * 2 * DCH;

        #pragma unroll 8
        for (int d = 0; d < DCH; ++d) {
            float2 xv = *(const float2*)&xsp[d * SX];
            u64 Y = *(const u64*)&ysp[d * SX];
            u64 W = *(const u64*)&wc[2 * d];
            u64 X0, X1;
            PK(X0, xv.x, xv.x);
            PK(X1, xv.y, xv.y);

            // ---- acc0 path: f32 tanh (2 MUFU) ----
            {
                u64 H, Q, S, U, T, G;
                float u0, u1, t0, t1;
                F2ADD(H, X0, Y);
                F2MUL(Q, H, H);
                F2FMA(S, Q, C1P, C0P);
                F2MUL(U, H, S);
                UNPK(u0, u1, U);
                t0 = tanh_fast(u0);
                t1 = tanh_fast(u1);
                PK(T, t0, t1);
                F2FMA(G, H, T, H);
                F2FMA(acc0, G, W, acc0);
            }

            // ---- acc1 path: f16x2 tanh (1 MUFU) ----
            {
                u64 H, Q, S, U, T, G;
                float u0, u1, t0, t1;
                unsigned tp;
                F2ADD(H, X1, Y);
                F2MUL(Q, H, H);
                F2FMA(S, Q, C1P, C0P);
                F2MUL(U, H, S);
                UNPK(u0, u1, U);
                asm("cvt.rn.f16x2.f32 %0, %1, %2;"
                    : "=r"(tp) : "f"(u1), "f"(u0));       // hi=u1, lo=u0
                asm("tanh.approx.f16x2 %0, %0;" : "+r"(tp));
                asm("{\n\t.reg .f16 lo, hi;\n\t"
                    "mov.b32 {lo, hi}, %2;\n\t"
                    "cvt.f32.f16 %0, lo;\n\t"
                    "cvt.f32.f16 %1, hi;\n\t}"
                    : "=f"(t0), "=f"(t1) : "r"(tp));
                PK(T, t0, t1);
                F2FMA(G, H, T, H);
                F2FMA(acc1, G, W, acc1);
            }
        }
    }

    const float bb = b2[0];
    u64 bpair; PK(bpair, bb, bb);
    F2ADD(acc0, acc0, bpair);
    F2ADD(acc1, acc1, bpair);

    const int n = n0 + 2 * ty;
    const int m = m0 + 2 * tx;
    float* orow = out + (size_t)(bz * NN + n) * NN + m;
    *(u64*)&orow[0]  = acc0;
    *(u64*)&orow[NN] = acc1;
}

// ---------------------------------------------------------------------------
extern "C" void kernel_launch(void* const* d_in, const int* in_sizes, int n_in,
                              void* d_out, int out_size)
{
    const float* x  = (const float*)d_in[0];
    const float* y  = (const float*)d_in[1];
    const float* W1 = (const float*)d_in[2];
    const float* b1 = (const float*)d_in[3];
    const float* W2 = (const float*)d_in[4];
    const float* b2 = (const float*)d_in[5];
    float* out = (float*)d_out;

    (void)in_sizes; (void)n_in; (void)out_size;

    const int smem_cross = (2 * DCH * SX + 512) * (int)sizeof(float);
    cudaFuncSetAttribute(cross_kernel,
                         cudaFuncAttributeMaxDynamicSharedMemorySize,
                         smem_cross);

    dim3 gblk(16, 16);
    dim3 ggrid(4, 32, 2);   // both GEMMs in one launch
    gemm_kernel<<<ggrid, gblk>>>(x, y, W1, b1);

    dim3 cblk(16, 16);
    dim3 cgrid(16, 16, 4);  // (m-tiles, n-tiles, batch)
    cross_kernel<<<cgrid, cblk, smem_cross>>>(W2, b2, out);
}

// round 7
// speedup vs baseline: 1.0311x; 1.0311x over previous
#include <cuda_runtime.h>
#include <math.h>

#define DD 256
#define BATCH 4
#define NN 512

typedef unsigned long long u64;

// Scratch: xp = x @ Wx  (B*N, D);  ypb = y @ Wy + b1  (B*N, D)
__device__ float g_xp[BATCH * NN * DD];
__device__ float g_ypb[BATCH * NN * DD];

// ---- f32x2 packed-math primitives (fma pipe, 2 fp32 per slot) -------------
#define F2FMA(D_, A_, B_, C_) \
    asm("fma.rn.f32x2 %0, %1, %2, %3;" : "=l"(D_) : "l"(A_), "l"(B_), "l"(C_))
#define F2ADD(D_, A_, B_) \
    asm("add.rn.f32x2 %0, %1, %2;" : "=l"(D_) : "l"(A_), "l"(B_))
#define F2MUL(D_, A_, B_) \
    asm("mul.rn.f32x2 %0, %1, %2;" : "=l"(D_) : "l"(A_), "l"(B_))
#define PK(D_, LO_, HI_) \
    asm("mov.b64 %0, {%1, %2};" : "=l"(D_) : "f"(LO_), "f"(HI_))
#define UNPK(LO_, HI_, S_) \
    asm("mov.b64 {%0, %1}, %2;" : "=f"(LO_), "=f"(HI_) : "l"(S_))

__device__ __forceinline__ float tanh_fast(float v) {
    float r;
    asm("tanh.approx.f32 %0, %1;" : "=f"(r) : "f"(v));
    return r;
}

#define GC0 0.79788456080286536f          // sqrt(2/pi)
#define GC1 0.03567740813636141f          // sqrt(2/pi)*0.044715

// ---------------------------------------------------------------------------
// Merged GEMM: z=0: g_xp = x @ W1[0:256];  z=1: g_ypb = y @ W1[256:512] + b1
// Tiles 32(m) x 64(n), BK=16, 128 threads, 4x4 per thread, f32x2 inner,
// double-buffered smem with register prefetch: 1 sync per K-chunk.
// grid (4, 64, 2) = 512 blocks.
// ---------------------------------------------------------------------------
__global__ __launch_bounds__(128) void gemm_kernel(
    const float* __restrict__ x,
    const float* __restrict__ y,
    const float* __restrict__ W1,
    const float* __restrict__ b1)
{
    __shared__ float Asd[2][16][70];   // [stage][k][2m(dup)]
    __shared__ float Bs[2][16][68];    // [stage][k][n]

    const int sel = blockIdx.z;
    const float* X = sel ? y : x;
    const float* W = sel ? (W1 + 256 * 256) : W1;
    float* out = sel ? g_ypb : g_xp;

    const int tx = threadIdx.x;     // 0..15 -> n
    const int ty = threadIdx.y;     // 0..7  -> m
    const int t  = ty * 16 + tx;
    const int m0 = blockIdx.y * 32;
    const int n0 = blockIdx.x * 64;

    // fill roles
    const int ma = t >> 2;          // 0..31  A row
    const int kq = (t & 3) * 4;     // A k quad
    const int kb = t >> 3;          // 0..15  B k row
    const int nq = (t & 7) * 8;     // B col octet

    u64 acc[4][2];
    #pragma unroll
    for (int i = 0; i < 4; ++i) { acc[i][0] = 0ull; acc[i][1] = 0ull; }

    // prologue: load chunk 0, store to stage 0
    float4 av  = *(const float4*)&X[(m0 + ma) * 256 + kq];
    float4 bv0 = *(const float4*)&W[kb * 256 + n0 + nq];
    float4 bv1 = *(const float4*)&W[kb * 256 + n0 + nq + 4];
    {
        u64 p;
        PK(p, av.x, av.x); *(u64*)&Asd[0][kq + 0][2 * ma] = p;
        PK(p, av.y, av.y); *(u64*)&Asd[0][kq + 1][2 * ma] = p;
        PK(p, av.z, av.z); *(u64*)&Asd[0][kq + 2][2 * ma] = p;
        PK(p, av.w, av.w); *(u64*)&Asd[0][kq + 3][2 * ma] = p;
        *(float4*)&Bs[0][kb][nq]     = bv0;
        *(float4*)&Bs[0][kb][nq + 4] = bv1;
    }
    __syncthreads();

    for (int kc = 0; kc < 16; ++kc) {
        const int s = kc & 1;
        if (kc < 15) {
            const int k0 = (kc + 1) * 16;
            av  = *(const float4*)&X[(m0 + ma) * 256 + k0 + kq];
            bv0 = *(const float4*)&W[(k0 + kb) * 256 + n0 + nq];
            bv1 = *(const float4*)&W[(k0 + kb) * 256 + n0 + nq + 4];
        }

        #pragma unroll
        for (int kk = 0; kk < 16; ++kk) {
            const float* ar = &Asd[s][kk][0];
            const float* br = &Bs[s][kk][0];
            u64 B0 = *(const u64*)&br[tx * 4];
            u64 B1 = *(const u64*)&br[tx * 4 + 2];
            #pragma unroll
            for (int i = 0; i < 4; ++i) {
                u64 Ai = *(const u64*)&ar[2 * (ty * 4 + i)];
                F2FMA(acc[i][0], Ai, B0, acc[i][0]);
                F2FMA(acc[i][1], Ai, B1, acc[i][1]);
            }
        }

        if (kc < 15) {
            const int s2 = s ^ 1;
            u64 p;
            PK(p, av.x, av.x); *(u64*)&Asd[s2][kq + 0][2 * ma] = p;
            PK(p, av.y, av.y); *(u64*)&Asd[s2][kq + 1][2 * ma] = p;
            PK(p, av.z, av.z); *(u64*)&Asd[s2][kq + 2][2 * ma] = p;
            PK(p, av.w, av.w); *(u64*)&Asd[s2][kq + 3][2 * ma] = p;
            *(float4*)&Bs[s2][kb][nq]     = bv0;
            *(float4*)&Bs[s2][kb][nq + 4] = bv1;
            __syncthreads();
        }
    }

    #pragma unroll
    for (int i = 0; i < 4; ++i) {
        int m = m0 + ty * 4 + i;
        int n = n0 + tx * 4;
        float c0, c1, c2, c3;
        UNPK(c0, c1, acc[i][0]);
        UNPK(c2, c3, acc[i][1]);
        if (sel) {
            c0 += b1[n + 0]; c1 += b1[n + 1];
            c2 += b1[n + 2]; c3 += b1[n + 3];
        }
        float4 o = {c0, c1, c2, c3};
        *(float4*)&out[m * 256 + n] = o;
    }
}

// ---------------------------------------------------------------------------
// Cross kernel (R5 form): block = (b, 32n x 32m) tile; thread = 2x2 micro-tile
// packed as two f32x2 groups. d chunked 2x128 -> 6 blocks/SM. f32 tanh.
// ---------------------------------------------------------------------------
#define SX 34       // row stride (floats): even for LDS.64 align, conflict-free
#define DCH 128     // d-chunk

__global__ __launch_bounds__(256, 6) void cross_kernel(
    const float* __restrict__ W2,
    const float* __restrict__ b2,
    float* __restrict__ out)
{
    extern __shared__ float sm[];
    float* xs  = sm;                     // [DCH][SX], d-major within chunk
    float* ys  = sm + DCH * SX;          // [DCH][SX]
    float* ws2 = sm + 2 * DCH * SX;      // [512] duplicated (0.5*W2 pairs)

    const int tx = threadIdx.x;        // 0..15 -> m
    const int ty = threadIdx.y;        // 0..15 -> n
    const int t  = ty * 16 + tx;
    const int bz = blockIdx.z;
    const int n0 = blockIdx.y * 32;
    const int m0 = blockIdx.x * 32;

    const float* xp = g_xp  + (bz * NN + n0) * DD;
    const float* yp = g_ypb + (bz * NN + m0) * DD;

    // ws2 once (all 256 d)
    {
        float wv = 0.5f * W2[t];
        u64 wp; PK(wp, wv, wv);
        *(u64*)&ws2[2 * t] = wp;
    }

    u64 C0P, C1P;
    PK(C0P, GC0, GC0);
    PK(C1P, GC1, GC1);

    u64 acc0 = 0ull, acc1 = 0ull;   // (a00,a01), (a10,a11)

    const int r  = t >> 3;    // 0..31
    const int cq = t & 7;     // 0..7
    const float* xsp = xs + 2 * ty;
    const float* ysp = ys + 2 * tx;

    #pragma unroll
    for (int c = 0; c < 2; ++c) {
        __syncthreads();   // (c=1: protect prior chunk's reads before refill)
        // Conflict-free transpose fill of this 128-d chunk
        #pragma unroll
        for (int it = 0; it < 4; ++it) {
            int dl = 32 * it + 4 * cq;           // 0..124 within chunk
            int dg = c * DCH + dl;               // global d
            float4 v = *(const float4*)&xp[r * 256 + dg];
            xs[(dl + 0) * SX + r] = v.x;
            xs[(dl + 1) * SX + r] = v.y;
            xs[(dl + 2) * SX + r] = v.z;
            xs[(dl + 3) * SX + r] = v.w;
            float4 u = *(const float4*)&yp[r * 256 + dg];
            ys[(dl + 0) * SX + r] = u.x;
            ys[(dl + 1) * SX + r] = u.y;
            ys[(dl + 2) * SX + r] = u.z;
            ys[(dl + 3) * SX + r] = u.w;
        }
        __syncthreads();

        const float* wc = ws2 + c * 2 * DCH;

        #pragma unroll 8
        for (int d = 0; d < DCH; ++d) {
            float2 xv = *(const float2*)&xsp[d * SX];
            u64 Y = *(const u64*)&ysp[d * SX];
            u64 W = *(const u64*)&wc[2 * d];
            u64 X0, X1;
            PK(X0, xv.x, xv.x);
            PK(X1, xv.y, xv.y);

            #define GEL2(ACC, XB)                               \
            {                                                   \
                u64 H, Q, S, U, T, G;                           \
                float u0, u1, t0, t1;                           \
                F2ADD(H, XB, Y);                                \
                F2MUL(Q, H, H);                                 \
                F2FMA(S, Q, C1P, C0P);                          \
                F2MUL(U, H, S);                                 \
                UNPK(u0, u1, U);                                \
                t0 = tanh_fast(u0);                             \
                t1 = tanh_fast(u1);                             \
                PK(T, t0, t1);                                  \
                F2FMA(G, H, T, H);                              \
                F2FMA(ACC, G, W, ACC);                          \
            }

            GEL2(acc0, X0)
            GEL2(acc1, X1)
            #undef GEL2
        }
    }

    const float bb = b2[0];
    u64 bpair; PK(bpair, bb, bb);
    F2ADD(acc0, acc0, bpair);
    F2ADD(acc1, acc1, bpair);

    const int n = n0 + 2 * ty;
    const int m = m0 + 2 * tx;
    float* orow = out + (size_t)(bz * NN + n) * NN + m;
    *(u64*)&orow[0]  = acc0;
    *(u64*)&orow[NN] = acc1;
}

// ---------------------------------------------------------------------------
extern "C" void kernel_launch(void* const* d_in, const int* in_sizes, int n_in,
                              void* d_out, int out_size)
{
    const float* x  = (const float*)d_in[0];
    const float* y  = (const float*)d_in[1];
    const float* W1 = (const float*)d_in[2];
    const float* b1 = (const float*)d_in[3];
    const float* W2 = (const float*)d_in[4];
    const float* b2 = (const float*)d_in[5];
    float* out = (float*)d_out;

    (void)in_sizes; (void)n_in; (void)out_size;

    const int smem_cross = (2 * DCH * SX + 512) * (int)sizeof(float);
    cudaFuncSetAttribute(cross_kernel,
                         cudaFuncAttributeMaxDynamicSharedMemorySize,
                         smem_cross);

    dim3 gblk(16, 8);
    dim3 ggrid(4, 64, 2);   // 64n-tiles x 32m-tiles x 2 gemms = 512 blocks
    gemm_kernel<<<ggrid, gblk>>>(x, y, W1, b1);

    dim3 cblk(16, 16);
    dim3 cgrid(16, 16, 4);  // (m-tiles, n-tiles, batch)
    cross_kernel<<<cgrid, cblk, smem_cross>>>(W2, b2, out);
}

// round 8
// speedup vs baseline: 1.0342x; 1.0031x over previous
#include <cuda_runtime.h>
#include <math.h>

#define DD 256
#define BATCH 4
#define NN 512

typedef unsigned long long u64;

// Scratch: xp = x @ Wx  (B*N, D);  ypb = y @ Wy + b1  (B*N, D)
__device__ float g_xp[BATCH * NN * DD];
__device__ float g_ypb[BATCH * NN * DD];

// ---- f32x2 packed-math primitives (fma pipe, 2 fp32 per slot) -------------
#define F2FMA(D_, A_, B_, C_) \
    asm("fma.rn.f32x2 %0, %1, %2, %3;" : "=l"(D_) : "l"(A_), "l"(B_), "l"(C_))
#define F2ADD(D_, A_, B_) \
    asm("add.rn.f32x2 %0, %1, %2;" : "=l"(D_) : "l"(A_), "l"(B_))
#define F2MUL(D_, A_, B_) \
    asm("mul.rn.f32x2 %0, %1, %2;" : "=l"(D_) : "l"(A_), "l"(B_))
#define PK(D_, LO_, HI_) \
    asm("mov.b64 %0, {%1, %2};" : "=l"(D_) : "f"(LO_), "f"(HI_))
#define UNPK(LO_, HI_, S_) \
    asm("mov.b64 {%0, %1}, %2;" : "=f"(LO_), "=f"(HI_) : "l"(S_))

__device__ __forceinline__ float tanh_fast(float v) {
    float r;
    asm("tanh.approx.f32 %0, %1;" : "=f"(r) : "f"(v));
    return r;
}

#define GC0 0.79788456080286536f          // sqrt(2/pi)
#define GC1 0.03567740813636141f          // sqrt(2/pi)*0.044715

// ---------------------------------------------------------------------------
// Merged GEMM: z=0: g_xp = x @ W1[0:256];  z=1: g_ypb = y @ W1[256:512] + b1
// Tiles 64(m) x 128(n), BK=16, 128 threads, 8x8 per thread, f32x2 inner.
// Grid (2, 32, 2) = 128 blocks -> 1 block/SM, single wave.
// A stored duplicated ([k][2m]=(a,a)) so LDS.128 yields 2 broadcast pairs.
// Double-buffered smem, register prefetch, 1 sync per K-chunk.
// ---------------------------------------------------------------------------
#define ARow 132    // floats per A smem row (528B, 16B-aligned)
#define BRow 132    // floats per B smem row

__global__ __launch_bounds__(128) void gemm_kernel(
    const float* __restrict__ x,
    const float* __restrict__ y,
    const float* __restrict__ W1,
    const float* __restrict__ b1)
{
    __shared__ float Asd[2][16][ARow];   // [stage][k][2m(dup)], 64 m
    __shared__ float Bs[2][16][BRow];    // [stage][k][n], 128 n

    const int sel = blockIdx.z;
    const float* X = sel ? y : x;
    const float* W = sel ? (W1 + 256 * 256) : W1;
    float* out = sel ? g_ypb : g_xp;

    const int tx = threadIdx.x;     // 0..15 -> n octet
    const int ty = threadIdx.y;     // 0..7  -> m octet
    const int t  = ty * 16 + tx;
    const int m0 = blockIdx.y * 64;
    const int n0 = blockIdx.x * 128;

    // fill roles
    const int fm   = t & 63;        // A row 0..63
    const int fkq  = (t >> 6) * 8;  // A k-offset {0, 8}
    const int fk   = t >> 3;        // B k row 0..15
    const int fnq  = (t & 7) * 16;  // B col offset 0..112

    u64 acc[8][4];
    #pragma unroll
    for (int i = 0; i < 8; ++i)
        #pragma unroll
        for (int j = 0; j < 4; ++j) acc[i][j] = 0ull;

    float4 pa0, pa1, pb0, pb1, pb2, pb3;

    // prologue: load + store chunk 0
    pa0 = *(const float4*)&X[(m0 + fm) * 256 + fkq];
    pa1 = *(const float4*)&X[(m0 + fm) * 256 + fkq + 4];
    pb0 = *(const float4*)&W[fk * 256 + n0 + fnq];
    pb1 = *(const float4*)&W[fk * 256 + n0 + fnq + 4];
    pb2 = *(const float4*)&W[fk * 256 + n0 + fnq + 8];
    pb3 = *(const float4*)&W[fk * 256 + n0 + fnq + 12];
    {
        u64 p;
        PK(p, pa0.x, pa0.x); *(u64*)&Asd[0][fkq + 0][2 * fm] = p;
        PK(p, pa0.y, pa0.y); *(u64*)&Asd[0][fkq + 1][2 * fm] = p;
        PK(p, pa0.z, pa0.z); *(u64*)&Asd[0][fkq + 2][2 * fm] = p;
        PK(p, pa0.w, pa0.w); *(u64*)&Asd[0][fkq + 3][2 * fm] = p;
        PK(p, pa1.x, pa1.x); *(u64*)&Asd[0][fkq + 4][2 * fm] = p;
        PK(p, pa1.y, pa1.y); *(u64*)&Asd[0][fkq + 5][2 * fm] = p;
        PK(p, pa1.z, pa1.z); *(u64*)&Asd[0][fkq + 6][2 * fm] = p;
        PK(p, pa1.w, pa1.w); *(u64*)&Asd[0][fkq + 7][2 * fm] = p;
        *(float4*)&Bs[0][fk][fnq]      = pb0;
        *(float4*)&Bs[0][fk][fnq + 4]  = pb1;
        *(float4*)&Bs[0][fk][fnq + 8]  = pb2;
        *(float4*)&Bs[0][fk][fnq + 12] = pb3;
    }
    __syncthreads();

    for (int kc = 0; kc < 16; ++kc) {
        const int s = kc & 1;
        if (kc < 15) {
            const int k0 = (kc + 1) * 16;
            pa0 = *(const float4*)&X[(m0 + fm) * 256 + k0 + fkq];
            pa1 = *(const float4*)&X[(m0 + fm) * 256 + k0 + fkq + 4];
            pb0 = *(const float4*)&W[(k0 + fk) * 256 + n0 + fnq];
            pb1 = *(const float4*)&W[(k0 + fk) * 256 + n0 + fnq + 4];
            pb2 = *(const float4*)&W[(k0 + fk) * 256 + n0 + fnq + 8];
            pb3 = *(const float4*)&W[(k0 + fk) * 256 + n0 + fnq + 12];
        }

        #pragma unroll
        for (int kk = 0; kk < 16; ++kk) {
            const float* ar = &Asd[s][kk][ty * 16];   // 8 dup pairs
            const float* br = &Bs[s][kk][tx * 8];     // 8 n
            u64 Ad[8], Bp[4];
            #pragma unroll
            for (int q = 0; q < 4; ++q) {             // 4 x LDS.128 (A)
                float4 av = *(const float4*)&ar[4 * q];
                u64 lo, hi;
                asm("mov.b64 %0, {%2, %3}; mov.b64 %1, {%4, %5};"
                    : "=l"(lo), "=l"(hi)
                    : "f"(av.x), "f"(av.y), "f"(av.z), "f"(av.w));
                Ad[2 * q]     = lo;
                Ad[2 * q + 1] = hi;
            }
            {
                float4 b0 = *(const float4*)&br[0];   // 2 x LDS.128 (B)
                float4 b1v = *(const float4*)&br[4];
                asm("mov.b64 %0, {%2, %3}; mov.b64 %1, {%4, %5};"
                    : "=l"(Bp[0]), "=l"(Bp[1])
                    : "f"(b0.x), "f"(b0.y), "f"(b0.z), "f"(b0.w));
                asm("mov.b64 %0, {%2, %3}; mov.b64 %1, {%4, %5};"
                    : "=l"(Bp[2]), "=l"(Bp[3])
                    : "f"(b1v.x), "f"(b1v.y), "f"(b1v.z), "f"(b1v.w));
            }
            #pragma unroll
            for (int i = 0; i < 8; ++i)
                #pragma unroll
                for (int j = 0; j < 4; ++j)
                    F2FMA(acc[i][j], Ad[i], Bp[j], acc[i][j]);
        }

        if (kc < 15) {
            const int s2 = s ^ 1;
            u64 p;
            PK(p, pa0.x, pa0.x); *(u64*)&Asd[s2][fkq + 0][2 * fm] = p;
            PK(p, pa0.y, pa0.y); *(u64*)&Asd[s2][fkq + 1][2 * fm] = p;
            PK(p, pa0.z, pa0.z); *(u64*)&Asd[s2][fkq + 2][2 * fm] = p;
            PK(p, pa0.w, pa0.w); *(u64*)&Asd[s2][fkq + 3][2 * fm] = p;
            PK(p, pa1.x, pa1.x); *(u64*)&Asd[s2][fkq + 4][2 * fm] = p;
            PK(p, pa1.y, pa1.y); *(u64*)&Asd[s2][fkq + 5][2 * fm] = p;
            PK(p, pa1.z, pa1.z); *(u64*)&Asd[s2][fkq + 6][2 * fm] = p;
            PK(p, pa1.w, pa1.w); *(u64*)&Asd[s2][fkq + 7][2 * fm] = p;
            *(float4*)&Bs[s2][fk][fnq]      = pb0;
            *(float4*)&Bs[s2][fk][fnq + 4]  = pb1;
            *(float4*)&Bs[s2][fk][fnq + 8]  = pb2;
            *(float4*)&Bs[s2][fk][fnq + 12] = pb3;
            __syncthreads();
        }
    }

    // epilogue
    float bias[8];
    if (sel) {
        float4 v0 = *(const float4*)&b1[n0 + tx * 8];
        float4 v1 = *(const float4*)&b1[n0 + tx * 8 + 4];
        bias[0] = v0.x; bias[1] = v0.y; bias[2] = v0.z; bias[3] = v0.w;
        bias[4] = v1.x; bias[5] = v1.y; bias[6] = v1.z; bias[7] = v1.w;
    }
    #pragma unroll
    for (int i = 0; i < 8; ++i) {
        int m = m0 + ty * 8 + i;
        int n = n0 + tx * 8;
        float c[8];
        UNPK(c[0], c[1], acc[i][0]);
        UNPK(c[2], c[3], acc[i][1]);
        UNPK(c[4], c[5], acc[i][2]);
        UNPK(c[6], c[7], acc[i][3]);
        if (sel) {
            #pragma unroll
            for (int j = 0; j < 8; ++j) c[j] += bias[j];
        }
        float4 o0 = {c[0], c[1], c[2], c[3]};
        float4 o1 = {c[4], c[5], c[6], c[7]};
        *(float4*)&out[m * 256 + n]     = o0;
        *(float4*)&out[m * 256 + n + 4] = o1;
    }
}

// ---------------------------------------------------------------------------
// Cross kernel (R5 form, unchanged): block = (b, 32n x 32m) tile; thread =
// 2x2 micro-tile as two f32x2 groups. d chunked 2x128 -> 6 blocks/SM.
// ---------------------------------------------------------------------------
#define SX 34       // row stride (floats): even for LDS.64 align, conflict-free
#define DCH 128     // d-chunk

__global__ __launch_bounds__(256, 6) void cross_kernel(
    const float* __restrict__ W2,
    const float* __restrict__ b2,
    float* __restrict__ out)
{
    extern __shared__ float sm[];
    float* xs  = sm;                     // [DCH][SX], d-major within chunk
    float* ys  = sm + DCH * SX;          // [DCH][SX]
    float* ws2 = sm + 2 * DCH * SX;      // [512] duplicated (0.5*W2 pairs)

    const int tx = threadIdx.x;        // 0..15 -> m
    const int ty = threadIdx.y;        // 0..15 -> n
    const int t  = ty * 16 + tx;
    const int bz = blockIdx.z;
    const int n0 = blockIdx.y * 32;
    const int m0 = blockIdx.x * 32;

    const float* xp = g_xp  + (bz * NN + n0) * DD;
    const float* yp = g_ypb + (bz * NN + m0) * DD;

    // ws2 once (all 256 d)
    {
        float wv = 0.5f * W2[t];
        u64 wp; PK(wp, wv, wv);
        *(u64*)&ws2[2 * t] = wp;
    }

    u64 C0P, C1P;
    PK(C0P, GC0, GC0);
    PK(C1P, GC1, GC1);

    u64 acc0 = 0ull, acc1 = 0ull;   // (a00,a01), (a10,a11)

    const int r  = t >> 3;    // 0..31
    const int cq = t & 7;     // 0..7
    const float* xsp = xs + 2 * ty;
    const float* ysp = ys + 2 * tx;

    #pragma unroll
    for (int c = 0; c < 2; ++c) {
        __syncthreads();   // (c=1: protect prior chunk's reads before refill)
        // Conflict-free transpose fill of this 128-d chunk
        #pragma unroll
        for (int it = 0; it < 4; ++it) {
            int dl = 32 * it + 4 * cq;           // 0..124 within chunk
            int dg = c * DCH + dl;               // global d
            float4 v = *(const float4*)&xp[r * 256 + dg];
            xs[(dl + 0) * SX + r] = v.x;
            xs[(dl + 1) * SX + r] = v.y;
            xs[(dl + 2) * SX + r] = v.z;
            xs[(dl + 3) * SX + r] = v.w;
            float4 u = *(const float4*)&yp[r * 256 + dg];
            ys[(dl + 0) * SX + r] = u.x;
            ys[(dl + 1) * SX + r] = u.y;
            ys[(dl + 2) * SX + r] = u.z;
            ys[(dl + 3) * SX + r] = u.w;
        }
        __syncthreads();

        const float* wc = ws2 + c * 2 * DCH;

        #pragma unroll 8
        for (int d = 0; d < DCH; ++d) {
            float2 xv = *(const float2*)&xsp[d * SX];
            u64 Y = *(const u64*)&ysp[d * SX];
            u64 W = *(const u64*)&wc[2 * d];
            u64 X0, X1;
            PK(X0, xv.x, xv.x);
            PK(X1, xv.y, xv.y);

            #define GEL2(ACC, XB)                               \
            {                                                   \
                u64 H, Q, S, U, T, G;                           \
                float u0, u1, t0, t1;                           \
                F2ADD(H, XB, Y);                                \
                F2MUL(Q, H, H);                                 \
                F2FMA(S, Q, C1P, C0P);                          \
                F2MUL(U, H, S);                                 \
                UNPK(u0, u1, U);                                \
                t0 = tanh_fast(u0);                             \
                t1 = tanh_fast(u1);                             \
                PK(T, t0, t1);                                  \
                F2FMA(G, H, T, H);                              \
                F2FMA(ACC, G, W, ACC);                          \
            }

            GEL2(acc0, X0)
            GEL2(acc1, X1)
            #undef GEL2
        }
    }

    const float bb = b2[0];
    u64 bpair; PK(bpair, bb, bb);
    F2ADD(acc0, acc0, bpair);
    F2ADD(acc1, acc1, bpair);

    const int n = n0 + 2 * ty;
    const int m = m0 + 2 * tx;
    float* orow = out + (size_t)(bz * NN + n) * NN + m;
    *(u64*)&orow[0]  = acc0;
    *(u64*)&orow[NN] = acc1;
}

// ---------------------------------------------------------------------------
extern "C" void kernel_launch(void* const* d_in, const int* in_sizes, int n_in,
                              void* d_out, int out_size)
{
    const float* x  = (const float*)d_in[0];
    const float* y  = (const float*)d_in[1];
    const float* W1 = (const float*)d_in[2];
    const float* b1 = (const float*)d_in[3];
    const float* W2 = (const float*)d_in[4];
    const float* b2 = (const float*)d_in[5];
    float* out = (float*)d_out;

    (void)in_sizes; (void)n_in; (void)out_size;

    const int smem_cross = (2 * DCH * SX + 512) * (int)sizeof(float);
    cudaFuncSetAttribute(cross_kernel,
                         cudaFuncAttributeMaxDynamicSharedMemorySize,
                         smem_cross);

    dim3 gblk(16, 8);       // 128 threads
    dim3 ggrid(2, 32, 2);   // 128 blocks: 2 n-tiles x 32 m-tiles x 2 gemms
    gemm_kernel<<<ggrid, gblk>>>(x, y, W1, b1);

    dim3 cblk(16, 16);
    dim3 cgrid(16, 16, 4);  // (m-tiles, n-tiles, batch)
    cross_kernel<<<cgrid, cblk, smem_cross>>>(W2, b2, out);
}

// round 9
// speedup vs baseline: 1.1046x; 1.0681x over previous
#include <cuda_runtime.h>
#include <math.h>

#define DD 256
#define BATCH 4
#define NN 512

typedef unsigned long long u64;

// Scratch: xp = x @ Wx  (B*N, D);  ypb = y @ Wy + b1  (B*N, D)
__device__ float g_xp[BATCH * NN * DD];
__device__ float g_ypb[BATCH * NN * DD];

// ---- f32x2 packed-math primitives (fma pipe, 2 fp32 per slot) -------------
#define F2FMA(D_, A_, B_, C_) \
    asm("fma.rn.f32x2 %0, %1, %2, %3;" : "=l"(D_) : "l"(A_), "l"(B_), "l"(C_))
#define F2ADD(D_, A_, B_) \
    asm("add.rn.f32x2 %0, %1, %2;" : "=l"(D_) : "l"(A_), "l"(B_))
#define F2MUL(D_, A_, B_) \
    asm("mul.rn.f32x2 %0, %1, %2;" : "=l"(D_) : "l"(A_), "l"(B_))
#define PK(D_, LO_, HI_) \
    asm("mov.b64 %0, {%1, %2};" : "=l"(D_) : "f"(LO_), "f"(HI_))
#define UNPK(LO_, HI_, S_) \
    asm("mov.b64 {%0, %1}, %2;" : "=f"(LO_), "=f"(HI_) : "l"(S_))

__device__ __forceinline__ float tanh_fast(float v) {
    float r;
    asm("tanh.approx.f32 %0, %1;" : "=f"(r) : "f"(v));
    return r;
}

#define GC0 0.79788456080286536f          // sqrt(2/pi)
#define GC1 0.03567740813636141f          // sqrt(2/pi)*0.044715

// ---------------------------------------------------------------------------
// Merged GEMM: z=0: g_xp = x @ W1[0:256];  z=1: g_ypb = y @ W1[256:512] + b1
// Scalar FFMA (proven fastest form), 64x64 tiles, BK=16, 256 threads, 4x4
// micro-tile. Double-buffered smem + register prefetch: ONE sync per K-chunk.
// Grid (4, 32, 2) = 256 blocks -> ~2 blocks/SM, single concurrent wave.
// ---------------------------------------------------------------------------
__global__ __launch_bounds__(256) void gemm_kernel(
    const float* __restrict__ x,
    const float* __restrict__ y,
    const float* __restrict__ W1,
    const float* __restrict__ b1)
{
    __shared__ float As[2][16][68];   // [stage][k][m] (A transposed)
    __shared__ float Bs[2][16][68];   // [stage][k][n]

    const int sel = blockIdx.z;
    const float* X = sel ? y : x;
    const float* W = sel ? (W1 + 256 * 256) : W1;
    float* out = sel ? g_ypb : g_xp;

    const int tx = threadIdx.x;     // 0..15
    const int ty = threadIdx.y;     // 0..15
    const int t  = ty * 16 + tx;
    const int m0 = blockIdx.y * 64;
    const int n0 = blockIdx.x * 64;

    // fill roles
    const int fm = t >> 2;          // A row 0..63
    const int fk = (t & 3) * 4;     // A k quad
    const int gk = t >> 4;          // B k row 0..15
    const int gn = (t & 15) * 4;    // B col quad

    float acc[4][4] = {};

    // prologue: chunk 0 -> stage 0
    float4 av = *(const float4*)&X[(m0 + fm) * 256 + fk];
    float4 bv = *(const float4*)&W[gk * 256 + n0 + gn];
    As[0][fk + 0][fm] = av.x;
    As[0][fk + 1][fm] = av.y;
    As[0][fk + 2][fm] = av.z;
    As[0][fk + 3][fm] = av.w;
    *(float4*)&Bs[0][gk][gn] = bv;
    __syncthreads();

    for (int kc = 0; kc < 16; ++kc) {
        const int s = kc & 1;
        if (kc < 15) {
            const int k0 = (kc + 1) * 16;
            av = *(const float4*)&X[(m0 + fm) * 256 + k0 + fk];
            bv = *(const float4*)&W[(k0 + gk) * 256 + n0 + gn];
        }

        #pragma unroll
        for (int kk = 0; kk < 16; ++kk) {
            float4 a = *(const float4*)&As[s][kk][ty * 4];
            float4 b = *(const float4*)&Bs[s][kk][tx * 4];
            float avr[4] = {a.x, a.y, a.z, a.w};
            float bvr[4] = {b.x, b.y, b.z, b.w};
            #pragma unroll
            for (int i = 0; i < 4; ++i)
                #pragma unroll
                for (int j = 0; j < 4; ++j)
                    acc[i][j] = fmaf(avr[i], bvr[j], acc[i][j]);
        }

        if (kc < 15) {
            const int s2 = s ^ 1;
            As[s2][fk + 0][fm] = av.x;
            As[s2][fk + 1][fm] = av.y;
            As[s2][fk + 2][fm] = av.z;
            As[s2][fk + 3][fm] = av.w;
            *(float4*)&Bs[s2][gk][gn] = bv;
            __syncthreads();
        }
    }

    #pragma unroll
    for (int i = 0; i < 4; ++i) {
        int m = m0 + ty * 4 + i;
        int n = n0 + tx * 4;
        float c0 = acc[i][0], c1 = acc[i][1], c2 = acc[i][2], c3 = acc[i][3];
        if (sel) {
            c0 += b1[n + 0]; c1 += b1[n + 1];
            c2 += b1[n + 2]; c3 += b1[n + 3];
        }
        float4 o = {c0, c1, c2, c3};
        *(float4*)&out[m * 256 + n] = o;
    }
}

// ---------------------------------------------------------------------------
// Cross kernel (R5 form, FROZEN): block = (b, 32n x 32m) tile; thread =
// 2x2 micro-tile as two f32x2 groups. d chunked 2x128 -> 6 blocks/SM.
// ---------------------------------------------------------------------------
#define SX 34       // row stride (floats): even for LDS.64 align, conflict-free
#define DCH 128     // d-chunk

__global__ __launch_bounds__(256, 6) void cross_kernel(
    const float* __restrict__ W2,
    const float* __restrict__ b2,
    float* __restrict__ out)
{
    extern __shared__ float sm[];
    float* xs  = sm;                     // [DCH][SX], d-major within chunk
    float* ys  = sm + DCH * SX;          // [DCH][SX]
    float* ws2 = sm + 2 * DCH * SX;      // [512] duplicated (0.5*W2 pairs)

    const int tx = threadIdx.x;        // 0..15 -> m
    const int ty = threadIdx.y;        // 0..15 -> n
    const int t  = ty * 16 + tx;
    const int bz = blockIdx.z;
    const int n0 = blockIdx.y * 32;
    const int m0 = blockIdx.x * 32;

    const float* xp = g_xp  + (bz * NN + n0) * DD;
    const float* yp = g_ypb + (bz * NN + m0) * DD;

    // ws2 once (all 256 d)
    {
        float wv = 0.5f * W2[t];
        u64 wp; PK(wp, wv, wv);
        *(u64*)&ws2[2 * t] = wp;
    }

    u64 C0P, C1P;
    PK(C0P, GC0, GC0);
    PK(C1P, GC1, GC1);

    u64 acc0 = 0ull, acc1 = 0ull;   // (a00,a01), (a10,a11)

    const int r  = t >> 3;    // 0..31
    const int cq = t & 7;     // 0..7
    const float* xsp = xs + 2 * ty;
    const float* ysp = ys + 2 * tx;

    #pragma unroll
    for (int c = 0; c < 2; ++c) {
        __syncthreads();   // (c=1: protect prior chunk's reads before refill)
        // Conflict-free transpose fill of this 128-d chunk
        #pragma unroll
        for (int it = 0; it < 4; ++it) {
            int dl = 32 * it + 4 * cq;           // 0..124 within chunk
            int dg = c * DCH + dl;               // global d
            float4 v = *(const float4*)&xp[r * 256 + dg];
            xs[(dl + 0) * SX + r] = v.x;
            xs[(dl + 1) * SX + r] = v.y;
            xs[(dl + 2) * SX + r] = v.z;
            xs[(dl + 3) * SX + r] = v.w;
            float4 u = *(const float4*)&yp[r * 256 + dg];
            ys[(dl + 0) * SX + r] = u.x;
            ys[(dl + 1) * SX + r] = u.y;
            ys[(dl + 2) * SX + r] = u.z;
            ys[(dl + 3) * SX + r] = u.w;
        }
        __syncthreads();

        const float* wc = ws2 + c * 2 * DCH;

        #pragma unroll 8
        for (int d = 0; d < DCH; ++d) {
            float2 xv = *(const float2*)&xsp[d * SX];
            u64 Y = *(const u64*)&ysp[d * SX];
            u64 W = *(const u64*)&wc[2 * d];
            u64 X0, X1;
            PK(X0, xv.x, xv.x);
            PK(X1, xv.y, xv.y);

            #define GEL2(ACC, XB)                               \
            {                                                   \
                u64 H, Q, S, U, T, G;                           \
                float u0, u1, t0, t1;                           \
                F2ADD(H, XB, Y);                                \
                F2MUL(Q, H, H);                                 \
                F2FMA(S, Q, C1P, C0P);                          \
                F2MUL(U, H, S);                                 \
                UNPK(u0, u1, U);                                \
                t0 = tanh_fast(u0);                             \
                t1 = tanh_fast(u1);                             \
                PK(T, t0, t1);                                  \
                F2FMA(G, H, T, H);                              \
                F2FMA(ACC, G, W, ACC);                          \
            }

            GEL2(acc0, X0)
            GEL2(acc1, X1)
            #undef GEL2
        }
    }

    const float bb = b2[0];
    u64 bpair; PK(bpair, bb, bb);
    F2ADD(acc0, acc0, bpair);
    F2ADD(acc1, acc1, bpair);

    const int n = n0 + 2 * ty;
    const int m = m0 + 2 * tx;
    float* orow = out + (size_t)(bz * NN + n) * NN + m;
    *(u64*)&orow[0]  = acc0;
    *(u64*)&orow[NN] = acc1;
}

// ---------------------------------------------------------------------------
extern "C" void kernel_launch(void* const* d_in, const int* in_sizes, int n_in,
                              void* d_out, int out_size)
{
    const float* x  = (const float*)d_in[0];
    const float* y  = (const float*)d_in[1];
    const float* W1 = (const float*)d_in[2];
    const float* b1 = (const float*)d_in[3];
    const float* W2 = (const float*)d_in[4];
    const float* b2 = (const float*)d_in[5];
    float* out = (float*)d_out;

    (void)in_sizes; (void)n_in; (void)out_size;

    const int smem_cross = (2 * DCH * SX + 512) * (int)sizeof(float);
    cudaFuncSetAttribute(cross_kernel,
                         cudaFuncAttributeMaxDynamicSharedMemorySize,
                         smem_cross);

    dim3 gblk(16, 16);      // 256 threads
    dim3 ggrid(4, 32, 2);   // 256 blocks, both GEMMs in one launch
    gemm_kernel<<<ggrid, gblk>>>(x, y, W1, b1);

    dim3 cblk(16, 16);
    dim3 cgrid(16, 16, 4);  // (m-tiles, n-tiles, batch)
    cross_kernel<<<cgrid, cblk, smem_cross>>>(W2, b2, out);
}

// round 10
// speedup vs baseline: 1.1342x; 1.0268x over previous
#include <cuda_runtime.h>
#include <math.h>

#define DD 256
#define BATCH 4
#define NN 512

typedef unsigned long long u64;

// Scratch: xp = x @ Wx  (B*N, D);  ypb = y @ Wy + b1  (B*N, D)
__device__ float g_xp[BATCH * NN * DD];
__device__ float g_ypb[BATCH * NN * DD];

// ---- f32x2 packed-math primitives (fma pipe, 2 fp32 per slot) -------------
#define F2FMA(D_, A_, B_, C_) \
    asm("fma.rn.f32x2 %0, %1, %2, %3;" : "=l"(D_) : "l"(A_), "l"(B_), "l"(C_))
#define F2ADD(D_, A_, B_) \
    asm("add.rn.f32x2 %0, %1, %2;" : "=l"(D_) : "l"(A_), "l"(B_))
#define F2MUL(D_, A_, B_) \
    asm("mul.rn.f32x2 %0, %1, %2;" : "=l"(D_) : "l"(A_), "l"(B_))
#define PK(D_, LO_, HI_) \
    asm("mov.b64 %0, {%1, %2};" : "=l"(D_) : "f"(LO_), "f"(HI_))
#define UNPK(LO_, HI_, S_) \
    asm("mov.b64 {%0, %1}, %2;" : "=f"(LO_), "=f"(HI_) : "l"(S_))

__device__ __forceinline__ float tanh_fast(float v) {
    float r;
    asm("tanh.approx.f32 %0, %1;" : "=f"(r) : "f"(v));
    return r;
}

#define GC0 0.79788456080286536f          // sqrt(2/pi)
#define GC1 0.03567740813636141f          // sqrt(2/pi)*0.044715

// ---------------------------------------------------------------------------
// Merged GEMM (R9 form, FROZEN): z=0: g_xp = x @ W1[0:256];
// z=1: g_ypb = y @ W1[256:512] + b1. 64x64 tiles, BK=16, 256 threads, 4x4
// micro-tile, double-buffered smem + register prefetch, 1 sync per K-chunk.
// ---------------------------------------------------------------------------
__global__ __launch_bounds__(256) void gemm_kernel(
    const float* __restrict__ x,
    const float* __restrict__ y,
    const float* __restrict__ W1,
    const float* __restrict__ b1)
{
    __shared__ float As[2][16][68];   // [stage][k][m] (A transposed)
    __shared__ float Bs[2][16][68];   // [stage][k][n]

    const int sel = blockIdx.z;
    const float* X = sel ? y : x;
    const float* W = sel ? (W1 + 256 * 256) : W1;
    float* out = sel ? g_ypb : g_xp;

    const int tx = threadIdx.x;     // 0..15
    const int ty = threadIdx.y;     // 0..15
    const int t  = ty * 16 + tx;
    const int m0 = blockIdx.y * 64;
    const int n0 = blockIdx.x * 64;

    // fill roles
    const int fm = t >> 2;          // A row 0..63
    const int fk = (t & 3) * 4;     // A k quad
    const int gk = t >> 4;          // B k row 0..15
    const int gn = (t & 15) * 4;    // B col quad

    float acc[4][4] = {};

    // prologue: chunk 0 -> stage 0
    float4 av = *(const float4*)&X[(m0 + fm) * 256 + fk];
    float4 bv = *(const float4*)&W[gk * 256 + n0 + gn];
    As[0][fk + 0][fm] = av.x;
    As[0][fk + 1][fm] = av.y;
    As[0][fk + 2][fm] = av.z;
    As[0][fk + 3][fm] = av.w;
    *(float4*)&Bs[0][gk][gn] = bv;
    __syncthreads();

    for (int kc = 0; kc < 16; ++kc) {
        const int s = kc & 1;
        if (kc < 15) {
            const int k0 = (kc + 1) * 16;
            av = *(const float4*)&X[(m0 + fm) * 256 + k0 + fk];
            bv = *(const float4*)&W[(k0 + gk) * 256 + n0 + gn];
        }

        #pragma unroll
        for (int kk = 0; kk < 16; ++kk) {
            float4 a = *(const float4*)&As[s][kk][ty * 4];
            float4 b = *(const float4*)&Bs[s][kk][tx * 4];
            float avr[4] = {a.x, a.y, a.z, a.w};
            float bvr[4] = {b.x, b.y, b.z, b.w};
            #pragma unroll
            for (int i = 0; i < 4; ++i)
                #pragma unroll
                for (int j = 0; j < 4; ++j)
                    acc[i][j] = fmaf(avr[i], bvr[j], acc[i][j]);
        }

        if (kc < 15) {
            const int s2 = s ^ 1;
            As[s2][fk + 0][fm] = av.x;
            As[s2][fk + 1][fm] = av.y;
            As[s2][fk + 2][fm] = av.z;
            As[s2][fk + 3][fm] = av.w;
            *(float4*)&Bs[s2][gk][gn] = bv;
            __syncthreads();
        }
    }

    #pragma unroll
    for (int i = 0; i < 4; ++i) {
        int m = m0 + ty * 4 + i;
        int n = n0 + tx * 4;
        float c0 = acc[i][0], c1 = acc[i][1], c2 = acc[i][2], c3 = acc[i][3];
        if (sel) {
            c0 += b1[n + 0]; c1 += b1[n + 1];
            c2 += b1[n + 2]; c3 += b1[n + 3];
        }
        float4 o = {c0, c1, c2, c3};
        *(float4*)&out[m * 256 + n] = o;
    }
}

// ---------------------------------------------------------------------------
// Cross kernel: block = (b, 32n x 32m) tile; thread = 2x2 micro-tile as two
// f32x2 groups. d chunked 4x64 with DOUBLE-BUFFERED smem + register prefetch:
// LDG of chunk c+1 overlaps compute of chunk c; one sync per chunk.
// ---------------------------------------------------------------------------
#define SX 34       // row stride (floats): even for LDS.64 align, conflict-free
#define DCH 64      // d-chunk (4 chunks of 64)

__global__ __launch_bounds__(256, 4) void cross_kernel(
    const float* __restrict__ W2,
    const float* __restrict__ b2,
    float* __restrict__ out)
{
    extern __shared__ float sm[];
    // xs[2][DCH*SX], ys[2][DCH*SX], ws2[512]
    float* xs0 = sm;
    float* ys0 = sm + 2 * DCH * SX;
    float* ws2 = sm + 4 * DCH * SX;

    const int tx = threadIdx.x;        // 0..15 -> m
    const int ty = threadIdx.y;        // 0..15 -> n
    const int t  = ty * 16 + tx;
    const int bz = blockIdx.z;
    const int n0 = blockIdx.y * 32;
    const int m0 = blockIdx.x * 32;

    const float* xp = g_xp  + (bz * NN + n0) * DD;
    const float* yp = g_ypb + (bz * NN + m0) * DD;

    // ws2 once (all 256 d)
    {
        float wv = 0.5f * W2[t];
        u64 wp; PK(wp, wv, wv);
        *(u64*)&ws2[2 * t] = wp;
    }

    u64 C0P, C1P;
    PK(C0P, GC0, GC0);
    PK(C1P, GC1, GC1);

    u64 acc0 = 0ull, acc1 = 0ull;   // (a00,a01), (a10,a11)

    const int r  = t >> 3;    // 0..31
    const int cq = t & 7;     // 0..7

    // prefetch registers: 2 x-float4 + 2 y-float4 per chunk
    float4 px[2], py[2];

    // prologue: LDG chunk 0, STS to buffer 0
    #pragma unroll
    for (int it = 0; it < 2; ++it) {
        int dg = 32 * it + 4 * cq;
        px[it] = *(const float4*)&xp[r * 256 + dg];
        py[it] = *(const float4*)&yp[r * 256 + dg];
    }
    #pragma unroll
    for (int it = 0; it < 2; ++it) {
        int dl = 32 * it + 4 * cq;
        xs0[(dl + 0) * SX + r] = px[it].x;
        xs0[(dl + 1) * SX + r] = px[it].y;
        xs0[(dl + 2) * SX + r] = px[it].z;
        xs0[(dl + 3) * SX + r] = px[it].w;
        ys0[(dl + 0) * SX + r] = py[it].x;
        ys0[(dl + 1) * SX + r] = py[it].y;
        ys0[(dl + 2) * SX + r] = py[it].z;
        ys0[(dl + 3) * SX + r] = py[it].w;
    }
    __syncthreads();

    #pragma unroll
    for (int c = 0; c < 4; ++c) {
        const int buf = c & 1;
        const float* xsb = xs0 + buf * DCH * SX;
        const float* ysb = ys0 + buf * DCH * SX;
        const float* xsp = xsb + 2 * ty;
        const float* ysp = ysb + 2 * tx;
        const float* wc  = ws2 + c * 2 * DCH;

        // prefetch chunk c+1 (overlaps compute below)
        if (c < 3) {
            #pragma unroll
            for (int it = 0; it < 2; ++it) {
                int dg = (c + 1) * DCH + 32 * it + 4 * cq;
                px[it] = *(const float4*)&xp[r * 256 + dg];
                py[it] = *(const float4*)&yp[r * 256 + dg];
            }
        }

        #pragma unroll 8
        for (int d = 0; d < DCH; ++d) {
            float2 xv = *(const float2*)&xsp[d * SX];
            u64 Y = *(const u64*)&ysp[d * SX];
            u64 W = *(const u64*)&wc[2 * d];
            u64 X0, X1;
            PK(X0, xv.x, xv.x);
            PK(X1, xv.y, xv.y);

            #define GEL2(ACC, XB)                               \
            {                                                   \
                u64 H, Q, S, U, T, G;                           \
                float u0, u1, t0, t1;                           \
                F2ADD(H, XB, Y);                                \
                F2MUL(Q, H, H);                                 \
                F2FMA(S, Q, C1P, C0P);                          \
                F2MUL(U, H, S);                                 \
                UNPK(u0, u1, U);                                \
                t0 = tanh_fast(u0);                             \
                t1 = tanh_fast(u1);                             \
                PK(T, t0, t1);                                  \
                F2FMA(G, H, T, H);                              \
                F2FMA(ACC, G, W, ACC);                          \
            }

            GEL2(acc0, X0)
            GEL2(acc1, X1)
            #undef GEL2
        }

        // store chunk c+1 into the other buffer, then sync
        if (c < 3) {
            float* xsn = xs0 + (buf ^ 1) * DCH * SX;
            float* ysn = ys0 + (buf ^ 1) * DCH * SX;
            #pragma unroll
            for (int it = 0; it < 2; ++it) {
                int dl = 32 * it + 4 * cq;
                xsn[(dl + 0) * SX + r] = px[it].x;
                xsn[(dl + 1) * SX + r] = px[it].y;
                xsn[(dl + 2) * SX + r] = px[it].z;
                xsn[(dl + 3) * SX + r] = px[it].w;
                ysn[(dl + 0) * SX + r] = py[it].x;
                ysn[(dl + 1) * SX + r] = py[it].y;
                ysn[(dl + 2) * SX + r] = py[it].z;
                ysn[(dl + 3) * SX + r] = py[it].w;
            }
            __syncthreads();
        }
    }

    const float bb = b2[0];
    u64 bpair; PK(bpair, bb, bb);
    F2ADD(acc0, acc0, bpair);
    F2ADD(acc1, acc1, bpair);

    const int n = n0 + 2 * ty;
    const int m = m0 + 2 * tx;
    float* orow = out + (size_t)(bz * NN + n) * NN + m;
    *(u64*)&orow[0]  = acc0;
    *(u64*)&orow[NN] = acc1;
}

// ---------------------------------------------------------------------------
extern "C" void kernel_launch(void* const* d_in, const int* in_sizes, int n_in,
                              void* d_out, int out_size)
{
    const float* x  = (const float*)d_in[0];
    const float* y  = (const float*)d_in[1];
    const float* W1 = (const float*)d_in[2];
    const float* b1 = (const float*)d_in[3];
    const float* W2 = (const float*)d_in[4];
    const float* b2 = (const float*)d_in[5];
    float* out = (float*)d_out;

    (void)in_sizes; (void)n_in; (void)out_size;

    const int smem_cross = (4 * DCH * SX + 512) * (int)sizeof(float);
    cudaFuncSetAttribute(cross_kernel,
                         cudaFuncAttributeMaxDynamicSharedMemorySize,
                         smem_cross);

    dim3 gblk(16, 16);      // 256 threads
    dim3 ggrid(4, 32, 2);   // 256 blocks, both GEMMs in one launch
    gemm_kernel<<<ggrid, gblk>>>(x, y, W1, b1);

    dim3 cblk(16, 16);
    dim3 cgrid(16, 16, 4);  // (m-tiles, n-tiles, batch)
    cross_kernel<<<cgrid, cblk, smem_cross>>>(W2, b2, out);
}